// round 16
// baseline (speedup 1.0000x reference)
#include <cuda_runtime.h>
#include <cuda_bf16.h>
#include <cstdint>

// Problem constants
#define B_    4
#define LS    512
#define DS    4096
#define DC    256
#define LC    512
#define NH    8
#define HD    64
#define INNER 512   // NH*HD

// ---------------------------------------------------------------------------
// Scratch (static __device__ globals)
// ---------------------------------------------------------------------------
__device__ __nv_bfloat16 g_Dh [(size_t)B_ * DS * DC];
__device__ __nv_bfloat16 g_Dl [(size_t)B_ * DS * DC];
__device__ __nv_bfloat16 g_Lh [(size_t)B_ * LS * LC];
__device__ __nv_bfloat16 g_Ll [(size_t)B_ * LS * LC];
__device__ __nv_bfloat16 g_Wqh[INNER * LC];
__device__ __nv_bfloat16 g_Wql[INNER * LC];
__device__ __nv_bfloat16 g_Wkh[INNER * DC];
__device__ __nv_bfloat16 g_Wkl[INNER * DC];
__device__ __nv_bfloat16 g_Wvh[INNER * DC];
__device__ __nv_bfloat16 g_Wvl[INNER * DC];
__device__ __nv_bfloat16 g_Woh[512 * INNER];
__device__ __nv_bfloat16 g_Wol[512 * INNER];
__device__ __nv_bfloat16 g_Qh [(size_t)B_ * LS * INNER];
__device__ __nv_bfloat16 g_Ql [(size_t)B_ * LS * INNER];
__device__ __nv_bfloat16 g_Kh [(size_t)B_ * DS * INNER];
__device__ __nv_bfloat16 g_Kl [(size_t)B_ * DS * INNER];
__device__ __nv_bfloat16 g_VTh[(size_t)B_ * INNER * DS];  // [(b*512+d)][key]
__device__ __nv_bfloat16 g_VTl[(size_t)B_ * INNER * DS];
__device__ __nv_bfloat16 g_AOh[(size_t)B_ * LS * INNER];
__device__ __nv_bfloat16 g_AOl[(size_t)B_ * LS * INNER];

// ---------------------------------------------------------------------------
// Common helpers
// ---------------------------------------------------------------------------
__device__ __forceinline__ uint32_t smem_u32(const void* p) {
    uint32_t a;
    asm("{ .reg .u64 t; cvta.to.shared.u64 t, %1; cvt.u32.u64 %0, t; }"
        : "=r"(a) : "l"(p));
    return a;
}
__device__ __forceinline__ void cp16(uint32_t saddr, const void* g) {
    asm volatile("cp.async.cg.shared.global [%0], [%1], 16;"
                 :: "r"(saddr), "l"(g) : "memory");
}
#define CP_COMMIT() asm volatile("cp.async.commit_group;" ::: "memory")
#define CP_WAIT(n)  asm volatile("cp.async.wait_group %0;" :: "n"(n) : "memory")

__device__ __forceinline__ uint32_t packbf2(__nv_bfloat16 a, __nv_bfloat16 b) {
    __nv_bfloat162 t; t.x = a; t.y = b;
    return *reinterpret_cast<uint32_t*>(&t);
}
__device__ __forceinline__ void split2(float a, float b, uint32_t& hi, uint32_t& lo) {
    const __nv_bfloat16 ha = __float2bfloat16(a);
    const __nv_bfloat16 hb = __float2bfloat16(b);
    hi = packbf2(ha, hb);
    lo = packbf2(__float2bfloat16(a - __bfloat162float(ha)),
                 __float2bfloat16(b - __bfloat162float(hb)));
}
__device__ __forceinline__ void mma_bf16(float* c, uint32_t a0, uint32_t a1,
                                         uint32_t a2, uint32_t a3,
                                         uint32_t b0, uint32_t b1)
{
    asm volatile(
        "mma.sync.aligned.m16n8k16.row.col.f32.bf16.bf16.f32 "
        "{%0,%1,%2,%3}, {%4,%5,%6,%7}, {%8,%9}, {%0,%1,%2,%3};"
        : "+f"(c[0]), "+f"(c[1]), "+f"(c[2]), "+f"(c[3])
        : "r"(a0), "r"(a1), "r"(a2), "r"(a3), "r"(b0), "r"(b1));
}

// ---------------------------------------------------------------------------
// fp32 -> bf16 hi/lo split
// ---------------------------------------------------------------------------
__global__ void __launch_bounds__(256)
splitf(const float* __restrict__ in, __nv_bfloat16* __restrict__ h,
       __nv_bfloat16* __restrict__ l, int n4)
{
    const int i = blockIdx.x * 256 + threadIdx.x;
    if (i >= n4) return;
    const float4 v = ((const float4*)in)[i];
    uint2 hw, lw;
    split2(v.x, v.y, hw.x, lw.x);
    split2(v.z, v.w, hw.y, lw.y);
    ((uint2*)h)[i] = hw;
    ((uint2*)l)[i] = lw;
}

// ---------------------------------------------------------------------------
// bf16-split HMMA GEMM with cp.async double-buffered mainloop.
// C[M,N] = A[M,K] @ B[N,K]^T, 3-term split. BM=BN=128, BK=32, 256 threads.
// Dynamic smem: 2 buffers x 4 tiles x (128 rows x 40 bf16) = 81920 B.
// MODE 0: fp32 + bias. MODE 1: bf16 hi/lo. MODE 2: transposed VT.
// ---------------------------------------------------------------------------
#define GPAD 40
#define GPW  20              // words per padded row
#define GT_BYTES 10240u      // one tile
#define GBUF_BYTES 40960u    // 4 tiles
#define HG_SMEM (2 * GBUF_BYTES)

template <int MODE>
__global__ void __launch_bounds__(256, 2)
hgemm(const __nv_bfloat16* __restrict__ Ah, const __nv_bfloat16* __restrict__ Al,
      const __nv_bfloat16* __restrict__ Bh, const __nv_bfloat16* __restrict__ Bl,
      const float* __restrict__ bias, float* __restrict__ C,
      __nv_bfloat16* __restrict__ Ch, __nv_bfloat16* __restrict__ Cl,
      int M, int N, int K)
{
    extern __shared__ char dsm[];
    const uint32_t sbase = smem_u32(dsm);
    uint32_t* SWD = reinterpret_cast<uint32_t*>(dsm);

    const int tid   = threadIdx.x;
    const int w     = tid >> 5;
    const int lane  = tid & 31;
    const int group = lane >> 2;
    const int tig   = lane & 3;
    const int mbase = (w & 3) * 32;
    const int nbase = (w >> 2) * 64;

    const __nv_bfloat16* Agh = Ah + (size_t)(blockIdx.y * 128) * K;
    const __nv_bfloat16* Agl = Al + (size_t)(blockIdx.y * 128) * K;
    const __nv_bfloat16* Bgh = Bh + (size_t)(blockIdx.x * 128) * K;
    const __nv_bfloat16* Bgl = Bl + (size_t)(blockIdx.x * 128) * K;

    // prefetch one 128x32 4-tile group into buffer buf
    const int pRow = tid >> 1;            // 0..127
    const int pC0  = (tid & 1) * 16;      // elem col 0 or 16
    auto prefetch = [&](int kt, int buf) {
        const size_t go = (size_t)pRow * K + kt * 32 + pC0;
        const uint32_t so = sbase + (uint32_t)buf * GBUF_BYTES
                          + (uint32_t)pRow * (GPAD * 2) + (uint32_t)pC0 * 2;
        cp16(so,                   Agh + go);
        cp16(so + 16,              Agh + go + 8);
        cp16(so + GT_BYTES,        Agl + go);
        cp16(so + GT_BYTES + 16,   Agl + go + 8);
        cp16(so + 2 * GT_BYTES,      Bgh + go);
        cp16(so + 2 * GT_BYTES + 16, Bgh + go + 8);
        cp16(so + 3 * GT_BYTES,      Bgl + go);
        cp16(so + 3 * GT_BYTES + 16, Bgl + go + 8);
    };

    float Cc[2][8][4];
#pragma unroll
    for (int mf = 0; mf < 2; mf++)
#pragma unroll
        for (int nf = 0; nf < 8; nf++)
#pragma unroll
            for (int e = 0; e < 4; e++) Cc[mf][nf][e] = 0.0f;

    const int NKI = K / 32;
    prefetch(0, 0);
    CP_COMMIT();

    for (int kt = 0; kt < NKI; kt++) {
        if (kt + 1 < NKI) {
            prefetch(kt + 1, (kt + 1) & 1);
            CP_COMMIT();
            CP_WAIT(1);
        } else {
            CP_WAIT(0);
        }
        __syncthreads();

        const uint32_t bw = (uint32_t)(kt & 1) * (GBUF_BYTES / 4);
        const uint32_t* WAh = SWD + bw;
        const uint32_t* WAl = SWD + bw + 2560;
        const uint32_t* WBh = SWD + bw + 5120;
        const uint32_t* WBl = SWD + bw + 7680;

#pragma unroll
        for (int ks = 0; ks < 2; ks++) {
            const int kw = ks * 8 + tig;
            uint32_t Afh[2][4], Afl[2][4];
#pragma unroll
            for (int mf = 0; mf < 2; mf++) {
                const int base = (mbase + mf * 16 + group) * GPW + kw;
                Afh[mf][0] = WAh[base];     Afh[mf][1] = WAh[base + 8 * GPW];
                Afh[mf][2] = WAh[base + 4]; Afh[mf][3] = WAh[base + 8 * GPW + 4];
                Afl[mf][0] = WAl[base];     Afl[mf][1] = WAl[base + 8 * GPW];
                Afl[mf][2] = WAl[base + 4]; Afl[mf][3] = WAl[base + 8 * GPW + 4];
            }
#pragma unroll
            for (int nf = 0; nf < 8; nf++) {
                const int bb = (nbase + nf * 8 + group) * GPW + kw;
                const uint32_t bh0 = WBh[bb], bh1 = WBh[bb + 4];
                const uint32_t bl0 = WBl[bb], bl1 = WBl[bb + 4];
#pragma unroll
                for (int mf = 0; mf < 2; mf++) {
                    mma_bf16(Cc[mf][nf], Afh[mf][0], Afh[mf][1], Afh[mf][2], Afh[mf][3], bh0, bh1);
                    mma_bf16(Cc[mf][nf], Afh[mf][0], Afh[mf][1], Afh[mf][2], Afh[mf][3], bl0, bl1);
                    mma_bf16(Cc[mf][nf], Afl[mf][0], Afl[mf][1], Afl[mf][2], Afl[mf][3], bh0, bh1);
                }
            }
        }
        __syncthreads();
    }

    // ---- epilogue ----
    const int growBase = blockIdx.y * 128 + mbase + group;
    const int gcolBase = blockIdx.x * 128 + nbase + tig * 2;
#pragma unroll
    for (int mf = 0; mf < 2; mf++) {
#pragma unroll
        for (int half = 0; half < 2; half++) {
            const int grow = growBase + mf * 16 + half * 8;
#pragma unroll
            for (int nf = 0; nf < 8; nf++) {
                const int gcol = gcolBase + nf * 8;
                const float v0 = Cc[mf][nf][half * 2 + 0];
                const float v1 = Cc[mf][nf][half * 2 + 1];
                if (MODE == 0) {
                    float2 o;
                    o.x = v0 + bias[gcol];
                    o.y = v1 + bias[gcol + 1];
                    *(float2*)(C + (size_t)grow * N + gcol) = o;
                } else if (MODE == 1) {
                    uint32_t hw, lw;
                    split2(v0, v1, hw, lw);
                    const size_t o = (size_t)grow * N + gcol;
                    *(uint32_t*)(Ch + o) = hw;
                    *(uint32_t*)(Cl + o) = lw;
                } else {
                    const int b   = grow >> 12;
                    const int key = grow & (DS - 1);
                    uint32_t hw, lw;
                    split2(v0, v1, hw, lw);
                    const __nv_bfloat16 h0 = __ushort_as_bfloat16((unsigned short)(hw & 0xffff));
                    const __nv_bfloat16 h1 = __ushort_as_bfloat16((unsigned short)(hw >> 16));
                    const __nv_bfloat16 l0 = __ushort_as_bfloat16((unsigned short)(lw & 0xffff));
                    const __nv_bfloat16 l1 = __ushort_as_bfloat16((unsigned short)(lw >> 16));
                    const size_t o0 = (size_t)(b * INNER + gcol)     * DS + key;
                    const size_t o1 = (size_t)(b * INNER + gcol + 1) * DS + key;
                    Ch[o0] = h0; Cl[o0] = l0;
                    Ch[o1] = h1; Cl[o1] = l1;
                }
            }
        }
    }
}

// ---------------------------------------------------------------------------
// mma.sync bf16 flash attention, cp.async double-buffered K/V.
// Grid (8 qb, 8 h, 4 b) = 256 CTAs, 128 threads (4 warps).
// smem words: QH 0, QL 2304, then per-buffer {KH,KL,VH,VL} of 2304 words:
// buf0 @4608, buf1 @13824. Total 23040 words = 92160 B (2 CTA/SM).
// ---------------------------------------------------------------------------
#define TPAD 72
#define TW   (TPAD / 2)          // 36 words/row
#define TILEW 2304               // words per 64x72 tile
#define W_QH 0
#define W_QL 2304
#define W_KV 4608                // buffer base (words); stride 4*TILEW = 9216
#define AT_SMEM ((4608 + 2 * 9216) * 4)   // 92160 B

__device__ __forceinline__ void ldtile_async(uint32_t sdst, const __nv_bfloat16* g,
                                             int gstride)
{
    const int tid = threadIdx.x;
    const int c   = (tid & 7) * 8;   // elem col (16B chunks)
    const int r0  = tid >> 3;        // 0..15
#pragma unroll
    for (int i = 0; i < 4; i++) {
        const int r = r0 + i * 16;
        cp16(sdst + (uint32_t)r * (TPAD * 2) + (uint32_t)c * 2,
             g + (size_t)r * gstride + c);
    }
}

__global__ void __launch_bounds__(128)
attn_mma(const __nv_bfloat16* __restrict__ Qh, const __nv_bfloat16* __restrict__ Ql,
         const __nv_bfloat16* __restrict__ Kh, const __nv_bfloat16* __restrict__ Kl,
         const __nv_bfloat16* __restrict__ VTh, const __nv_bfloat16* __restrict__ VTl,
         __nv_bfloat16* __restrict__ AOh, __nv_bfloat16* __restrict__ AOl)
{
    extern __shared__ __nv_bfloat16 smem[];
    const uint32_t sbase = smem_u32(smem);
    uint32_t* SW = reinterpret_cast<uint32_t*>(smem);

    const int tid   = threadIdx.x;
    const int w     = tid >> 5;
    const int lane  = tid & 31;
    const int group = lane >> 2;
    const int tig   = lane & 3;
    const int qb = blockIdx.x, h = blockIdx.y, b = blockIdx.z;

    const size_t qrow0 = (size_t)(b * LS + qb * 64);
    const __nv_bfloat16* gQh = Qh + qrow0 * INNER + h * HD;
    const __nv_bfloat16* gQl = Ql + qrow0 * INNER + h * HD;
    const __nv_bfloat16* gKh = Kh + (size_t)b * DS * INNER + h * HD;
    const __nv_bfloat16* gKl = Kl + (size_t)b * DS * INNER + h * HD;
    const __nv_bfloat16* gVh = VTh + (size_t)(b * INNER + h * HD) * DS;
    const __nv_bfloat16* gVl = VTl + (size_t)(b * INNER + h * HD) * DS;

    auto prefetch_kv = [&](int t, int buf) {
        const uint32_t base = sbase + (uint32_t)(W_KV + buf * 9216) * 4;
        ldtile_async(base,                 gKh + (size_t)t * 64 * INNER, INNER);
        ldtile_async(base + TILEW * 4,     gKl + (size_t)t * 64 * INNER, INNER);
        ldtile_async(base + 2 * TILEW * 4, gVh + (size_t)t * 64, DS);
        ldtile_async(base + 3 * TILEW * 4, gVl + (size_t)t * 64, DS);
    };

    // Q tiles + first KV tile in one group
    ldtile_async(sbase + W_QH * 4, gQh, INNER);
    ldtile_async(sbase + W_QL * 4, gQl, INNER);
    prefetch_kv(0, 0);
    CP_COMMIT();

    float Oc[8][4];
#pragma unroll
    for (int n = 0; n < 8; n++)
#pragma unroll
        for (int e = 0; e < 4; e++) Oc[n][e] = 0.0f;
    float l0 = 0.0f, l1 = 0.0f;

    const int arow  = (16 * w + group) * TW;
    const int arow8 = arow + 8 * TW;
    const int NT = DS / 64;

    for (int t = 0; t < NT; t++) {
        if (t + 1 < NT) {
            prefetch_kv(t + 1, (t + 1) & 1);
            CP_COMMIT();
            CP_WAIT(1);
        } else {
            CP_WAIT(0);
        }
        __syncthreads();

        const int kvw = W_KV + (t & 1) * 9216;
        const int oKH = kvw, oKL = kvw + TILEW, oVH = kvw + 2 * TILEW, oVL = kvw + 3 * TILEW;

        // ---- S = Q K^T (3-term split) ----
        float Sc[8][4];
#pragma unroll
        for (int n = 0; n < 8; n++)
#pragma unroll
            for (int e = 0; e < 4; e++) Sc[n][e] = 0.0f;

#pragma unroll
        for (int kk = 0; kk < 4; kk++) {
            const int aw  = arow + kk * 8 + tig;
            const int aw8 = arow8 + kk * 8 + tig;
            const uint32_t ah0 = SW[W_QH + aw],     ah1 = SW[W_QH + aw8];
            const uint32_t ah2 = SW[W_QH + aw + 4], ah3 = SW[W_QH + aw8 + 4];
            const uint32_t al0 = SW[W_QL + aw],     al1 = SW[W_QL + aw8];
            const uint32_t al2 = SW[W_QL + aw + 4], al3 = SW[W_QL + aw8 + 4];
#pragma unroll
            for (int n = 0; n < 8; n++) {
                const int bw = (n * 8 + group) * TW + kk * 8 + tig;
                const uint32_t bh0 = SW[oKH + bw], bh1 = SW[oKH + bw + 4];
                const uint32_t bl0 = SW[oKL + bw], bl1 = SW[oKL + bw + 4];
                mma_bf16(Sc[n], ah0, ah1, ah2, ah3, bh0, bh1);
                mma_bf16(Sc[n], ah0, ah1, ah2, ah3, bl0, bl1);
                mma_bf16(Sc[n], al0, al1, al2, al3, bh0, bh1);
            }
        }

        // ---- softmax, static max: p = exp(0.125 s - 16) ----
#pragma unroll
        for (int n = 0; n < 8; n++) {
            const float p0 = __expf(fmaf(Sc[n][0], 0.125f, -16.0f));
            const float p1 = __expf(fmaf(Sc[n][1], 0.125f, -16.0f));
            const float p2 = __expf(fmaf(Sc[n][2], 0.125f, -16.0f));
            const float p3 = __expf(fmaf(Sc[n][3], 0.125f, -16.0f));
            Sc[n][0] = p0; Sc[n][1] = p1; Sc[n][2] = p2; Sc[n][3] = p3;
            l0 += p0 + p1;
            l1 += p2 + p3;
        }

        // ---- O += P V (3-term split) ----
#pragma unroll
        for (int j = 0; j < 4; j++) {
            uint32_t ah0, ah1, ah2, ah3, al0, al1, al2, al3;
            split2(Sc[2*j][0],     Sc[2*j][1],     ah0, al0);
            split2(Sc[2*j][2],     Sc[2*j][3],     ah1, al1);
            split2(Sc[2*j + 1][0], Sc[2*j + 1][1], ah2, al2);
            split2(Sc[2*j + 1][2], Sc[2*j + 1][3], ah3, al3);
#pragma unroll
            for (int n = 0; n < 8; n++) {
                const int bw = (n * 8 + group) * TW + j * 8 + tig;
                const uint32_t bh0 = SW[oVH + bw], bh1 = SW[oVH + bw + 4];
                const uint32_t bl0 = SW[oVL + bw], bl1 = SW[oVL + bw + 4];
                mma_bf16(Oc[n], ah0, ah1, ah2, ah3, bh0, bh1);
                mma_bf16(Oc[n], al0, al1, al2, al3, bh0, bh1);
                mma_bf16(Oc[n], ah0, ah1, ah2, ah3, bl0, bl1);
            }
        }
        __syncthreads();   // compute done before next prefetch overwrites this buffer
    }

#pragma unroll
    for (int m = 1; m < 4; m <<= 1) {
        l0 += __shfl_xor_sync(0xffffffffu, l0, m);
        l1 += __shfl_xor_sync(0xffffffffu, l1, m);
    }
    const float inv0 = 1.0f / l0;
    const float inv1 = 1.0f / l1;

    const size_t r0o = (qrow0 + 16 * w + group)     * INNER + h * HD;
    const size_t r1o = (qrow0 + 16 * w + group + 8) * INNER + h * HD;
#pragma unroll
    for (int n = 0; n < 8; n++) {
        const int d = n * 8 + 2 * tig;
        uint32_t hw, lw;
        split2(Oc[n][0] * inv0, Oc[n][1] * inv0, hw, lw);
        *(uint32_t*)(AOh + r0o + d) = hw;
        *(uint32_t*)(AOl + r0o + d) = lw;
        split2(Oc[n][2] * inv1, Oc[n][3] * inv1, hw, lw);
        *(uint32_t*)(AOh + r1o + d) = hw;
        *(uint32_t*)(AOl + r1o + d) = lw;
    }
}

// ---------------------------------------------------------------------------
// Launcher
// ---------------------------------------------------------------------------
extern "C" void kernel_launch(void* const* d_in, const int* in_sizes, int n_in,
                              void* d_out, int out_size)
{
    const float* data   = (const float*)d_in[0];
    const float* latent = (const float*)d_in[1];
    const float* Wq     = (const float*)d_in[2];
    const float* Wk     = (const float*)d_in[3];
    const float* Wv     = (const float*)d_in[4];
    const float* Wo     = (const float*)d_in[5];
    const float* bo     = (const float*)d_in[6];
    float*       out    = (float*)d_out;

    __nv_bfloat16 *pDh, *pDl, *pLh, *pLl;
    __nv_bfloat16 *pWqh, *pWql, *pWkh, *pWkl, *pWvh, *pWvl, *pWoh, *pWol;
    __nv_bfloat16 *pQh, *pQl, *pKh, *pKl, *pVh, *pVl, *pAOh, *pAOl;
    cudaGetSymbolAddress((void**)&pDh,  g_Dh);
    cudaGetSymbolAddress((void**)&pDl,  g_Dl);
    cudaGetSymbolAddress((void**)&pLh,  g_Lh);
    cudaGetSymbolAddress((void**)&pLl,  g_Ll);
    cudaGetSymbolAddress((void**)&pWqh, g_Wqh);
    cudaGetSymbolAddress((void**)&pWql, g_Wql);
    cudaGetSymbolAddress((void**)&pWkh, g_Wkh);
    cudaGetSymbolAddress((void**)&pWkl, g_Wkl);
    cudaGetSymbolAddress((void**)&pWvh, g_Wvh);
    cudaGetSymbolAddress((void**)&pWvl, g_Wvl);
    cudaGetSymbolAddress((void**)&pWoh, g_Woh);
    cudaGetSymbolAddress((void**)&pWol, g_Wol);
    cudaGetSymbolAddress((void**)&pQh,  g_Qh);
    cudaGetSymbolAddress((void**)&pQl,  g_Ql);
    cudaGetSymbolAddress((void**)&pKh,  g_Kh);
    cudaGetSymbolAddress((void**)&pKl,  g_Kl);
    cudaGetSymbolAddress((void**)&pVh,  g_VTh);
    cudaGetSymbolAddress((void**)&pVl,  g_VTl);
    cudaGetSymbolAddress((void**)&pAOh, g_AOh);
    cudaGetSymbolAddress((void**)&pAOl, g_AOl);

    cudaFuncSetAttribute(attn_mma, cudaFuncAttributeMaxDynamicSharedMemorySize, AT_SMEM);
    cudaFuncSetAttribute(hgemm<0>, cudaFuncAttributeMaxDynamicSharedMemorySize, HG_SMEM);
    cudaFuncSetAttribute(hgemm<1>, cudaFuncAttributeMaxDynamicSharedMemorySize, HG_SMEM);
    cudaFuncSetAttribute(hgemm<2>, cudaFuncAttributeMaxDynamicSharedMemorySize, HG_SMEM);

    // ---- fp32 -> bf16 hi/lo splits ----
    const int nData   = B_ * DS * DC / 4;
    const int nLatent = B_ * LS * LC / 4;
    const int nWq     = INNER * LC / 4;
    const int nWk     = INNER * DC / 4;
    const int nWo     = 512 * INNER / 4;
    splitf<<<(nData   + 255) / 256, 256>>>(data,   pDh,  pDl,  nData);
    splitf<<<(nLatent + 255) / 256, 256>>>(latent, pLh,  pLl,  nLatent);
    splitf<<<(nWq     + 255) / 256, 256>>>(Wq,     pWqh, pWql, nWq);
    splitf<<<(nWk     + 255) / 256, 256>>>(Wk,     pWkh, pWkl, nWk);
    splitf<<<(nWk     + 255) / 256, 256>>>(Wv,     pWvh, pWvl, nWk);
    splitf<<<(nWo     + 255) / 256, 256>>>(Wo,     pWoh, pWol, nWo);

    // ---- projections (bf16-split HMMA, cp.async pipelined) ----
    hgemm<1><<<dim3(INNER / 128, (B_ * DS) / 128), 256, HG_SMEM>>>(
        pDh, pDl, pWkh, pWkl, nullptr, nullptr, pKh, pKl, B_ * DS, INNER, DC);
    hgemm<2><<<dim3(INNER / 128, (B_ * DS) / 128), 256, HG_SMEM>>>(
        pDh, pDl, pWvh, pWvl, nullptr, nullptr, pVh, pVl, B_ * DS, INNER, DC);
    hgemm<1><<<dim3(INNER / 128, (B_ * LS) / 128), 256, HG_SMEM>>>(
        pLh, pLl, pWqh, pWql, nullptr, nullptr, pQh, pQl, B_ * LS, INNER, LC);
    // ---- flash attention ----
    attn_mma<<<dim3(LS / 64, NH, B_), 128, AT_SMEM>>>(
        pQh, pQl, pKh, pKl, pVh, pVl, pAOh, pAOl);
    // ---- out = AO @ Wo^T + bo ----
    hgemm<0><<<dim3(512 / 128, (B_ * LS) / 128), 256, HG_SMEM>>>(
        pAOh, pAOl, pWoh, pWol, bo, out, nullptr, nullptr, B_ * LS, 512, INNER);
}